// round 1
// baseline (speedup 1.0000x reference)
#include <cuda_runtime.h>
#include <cuda_bf16.h>

// Problem constants
#define BATCH   4
#define LENGTH  512
#define DMODEL  128
#define DINNER  256
#define DSTATE  256
#define MROWS   (BATCH * LENGTH)        // 2048
#define LOG2E   1.4426950408889634f

// Scratch (allocation-free: __device__ globals)
__device__ float g_xs[MROWS * DINNER];     // xs (first half of in_proj)
__device__ float g_sz[MROWS * DINNER];     // silu(z)
__device__ float g_delta[MROWS * DINNER];  // xs @ W_delta
__device__ float g_bu[MROWS * DSTATE];     // (xs @ W_B) * xs   (elementwise)
__device__ float g_Cv[MROWS * DINNER];     // xs @ W_C
__device__ float g_y[MROWS * DINNER];      // scan output * silu(z)

// ---------------------------------------------------------------------------
// Tiled fp32 GEMM: C[64x64] per block, 128 threads, thread tile 8x4.
// MODE 0: x(2048x128) @ W_in(128x512)  -> split: xs | silu(z)
// MODE 1: g_xs(2048x256) @ {W_delta,W_B,W_C}(256x256) -> delta | bu | Cv
// MODE 2: g_y(2048x256) @ W_out(256x128) -> d_out
// lda == K in all modes.
// ---------------------------------------------------------------------------
template <int MODE>
__global__ __launch_bounds__(128)
void gemm_kernel(const float* __restrict__ Ag_,
                 const float* __restrict__ B0,
                 const float* __restrict__ B1,
                 const float* __restrict__ B2,
                 float* __restrict__ Og)
{
    constexpr int K   = (MODE == 0) ? 128 : 256;
    constexpr int LDB = (MODE == 0) ? 512 : ((MODE == 1) ? 256 : 128);

    __shared__ float As[16][68];   // transposed A tile, padded (68: 16B-aligned rows, 2-way max conflict)
    __shared__ float Bs[16][68];

    const int tid = threadIdx.x;
    const int tx  = tid & 15;      // 16 column groups of 4
    const int ty  = tid >> 4;      // 8 row groups of 8
    const int m0  = blockIdx.y * 64;

    const float* Ag;
    const float* Bg;
    int n0;
    int which = 0;
    if (MODE == 1) {
        which = blockIdx.x >> 2;              // 0: W_delta, 1: W_B, 2: W_C
        n0 = (blockIdx.x & 3) * 64;
        Bg = (which == 0) ? B0 : ((which == 1) ? B1 : B2);
        Ag = g_xs;
    } else {
        n0 = blockIdx.x * 64;
        Bg = B0;
        Ag = (MODE == 0) ? Ag_ : g_y;
    }

    float acc[8][4];
#pragma unroll
    for (int i = 0; i < 8; i++)
#pragma unroll
        for (int j = 0; j < 4; j++) acc[i][j] = 0.f;

    for (int k0 = 0; k0 < K; k0 += 16) {
        // A tile: 64 rows x 16 cols, stored transposed As[k][m]
#pragma unroll
        for (int r = 0; r < 2; r++) {
            int idx = tid + r * 128;
            int row = idx >> 2;
            int c4  = (idx & 3) << 2;
            float4 v = *(const float4*)(Ag + (size_t)(m0 + row) * K + k0 + c4);
            As[c4 + 0][row] = v.x;
            As[c4 + 1][row] = v.y;
            As[c4 + 2][row] = v.z;
            As[c4 + 3][row] = v.w;
        }
        // B tile: 16 rows x 64 cols
#pragma unroll
        for (int r = 0; r < 2; r++) {
            int idx  = tid + r * 128;
            int rowk = idx >> 4;
            int c4   = (idx & 15) << 2;
            *(float4*)&Bs[rowk][c4] =
                *(const float4*)(Bg + (size_t)(k0 + rowk) * LDB + n0 + c4);
        }
        __syncthreads();

#pragma unroll
        for (int kk = 0; kk < 16; kk++) {
            float4 a0 = *(const float4*)&As[kk][ty * 8];
            float4 a1 = *(const float4*)&As[kk][ty * 8 + 4];
            float4 bb = *(const float4*)&Bs[kk][tx * 4];
            float a[8] = {a0.x, a0.y, a0.z, a0.w, a1.x, a1.y, a1.z, a1.w};
            float bv[4] = {bb.x, bb.y, bb.z, bb.w};
#pragma unroll
            for (int i = 0; i < 8; i++)
#pragma unroll
                for (int j = 0; j < 4; j++)
                    acc[i][j] = fmaf(a[i], bv[j], acc[i][j]);
        }
        __syncthreads();
    }

    // Epilogue
#pragma unroll
    for (int i = 0; i < 8; i++) {
        int m = m0 + ty * 8 + i;
#pragma unroll
        for (int j = 0; j < 4; j++) {
            int c = n0 + tx * 4 + j;
            float v = acc[i][j];
            if (MODE == 0) {
                if (c < 256) {
                    g_xs[m * 256 + c] = v;
                } else {
                    float sig = 1.f / (1.f + __expf(-v));
                    g_sz[m * 256 + (c - 256)] = v * sig;   // silu(z)
                }
            } else if (MODE == 1) {
                if (which == 0)      g_delta[m * 256 + c] = v;
                else if (which == 1) g_bu[m * 256 + c] = v * g_xs[m * 256 + c];
                else                 g_Cv[m * 256 + c] = v;
            } else {
                Og[m * 128 + c] = v;
            }
        }
    }
}

// ---------------------------------------------------------------------------
// Sequential selective scan. One warp per (b, d): 1024 warps = 256 blocks x 4.
// Each lane owns 8 contiguous n's of the 256-wide state, kept in registers.
// Per step: e = ex2(delta * (A*log2e)); s = e*s + delta*bu[n]; y += s*C[n];
// warp-shfl reduce -> y[b,t,d] * silu(z)[b,t,d].
// Next-step operands are prefetched to hide memory latency behind the chain.
// ---------------------------------------------------------------------------
__global__ __launch_bounds__(128)
void scan_kernel(const float* __restrict__ A)
{
    const int warp = threadIdx.x >> 5;
    const int lane = threadIdx.x & 31;
    const int b    = blockIdx.x >> 6;                 // 64 blocks per batch
    const int d    = ((blockIdx.x & 63) << 2) | warp; // 4 d's per block (same b -> L1 sharing)
    const int nb   = lane << 3;                       // this lane's n base (32B aligned)

    float Ae[8];
#pragma unroll
    for (int j = 0; j < 8; j++)
        Ae[j] = A[d * 256 + nb + j] * LOG2E;          // fold log2(e) into A once

    const int base = b * LENGTH * 256;
    const float* __restrict__ bu  = g_bu    + base;
    const float* __restrict__ Cp  = g_Cv    + base;
    const float* __restrict__ dp  = g_delta + base;
    const float* __restrict__ szp = g_sz    + base;
    float*       __restrict__ yp  = g_y     + base;

    float s[8];
#pragma unroll
    for (int j = 0; j < 8; j++) s[j] = 0.f;

    float bucur[8], ccur[8];
    *(float4*)&bucur[0] = *(const float4*)(bu + nb);
    *(float4*)&bucur[4] = *(const float4*)(bu + nb + 4);
    *(float4*)&ccur[0]  = *(const float4*)(Cp + nb);
    *(float4*)&ccur[4]  = *(const float4*)(Cp + nb + 4);
    float delta = dp[d];

    for (int t = 0; t < LENGTH; t++) {
        // prefetch t+1 (clamped) while computing t
        const int off = ((t + 1 < LENGTH) ? (t + 1) : t) * 256;
        float bunx[8], cnx[8];
        *(float4*)&bunx[0] = *(const float4*)(bu + off + nb);
        *(float4*)&bunx[4] = *(const float4*)(bu + off + nb + 4);
        *(float4*)&cnx[0]  = *(const float4*)(Cp + off + nb);
        *(float4*)&cnx[4]  = *(const float4*)(Cp + off + nb + 4);
        const float dnx = dp[off + d];

        float yacc = 0.f;
#pragma unroll
        for (int j = 0; j < 8; j++) {
            float p = delta * Ae[j];
            float e;
            asm("ex2.approx.ftz.f32 %0, %1;" : "=f"(e) : "f"(p));
            s[j] = fmaf(e, s[j], delta * bucur[j]);
            yacc = fmaf(s[j], ccur[j], yacc);
        }
        // warp reduction over the 256 n's
        yacc += __shfl_xor_sync(0xffffffffu, yacc, 16);
        yacc += __shfl_xor_sync(0xffffffffu, yacc, 8);
        yacc += __shfl_xor_sync(0xffffffffu, yacc, 4);
        yacc += __shfl_xor_sync(0xffffffffu, yacc, 2);
        yacc += __shfl_xor_sync(0xffffffffu, yacc, 1);
        if (lane == 0)
            yp[t * 256 + d] = yacc * szp[t * 256 + d];   // fuse * silu(z)

#pragma unroll
        for (int j = 0; j < 8; j++) { bucur[j] = bunx[j]; ccur[j] = cnx[j]; }
        delta = dnx;
    }
}

// ---------------------------------------------------------------------------
// Inputs (metadata order): x, W_in, W_delta, W_B, W_C, W_out, A, D(unused)
// ---------------------------------------------------------------------------
extern "C" void kernel_launch(void* const* d_in, const int* in_sizes, int n_in,
                              void* d_out, int out_size)
{
    const float* x       = (const float*)d_in[0];
    const float* W_in    = (const float*)d_in[1];
    const float* W_delta = (const float*)d_in[2];
    const float* W_B     = (const float*)d_in[3];
    const float* W_C     = (const float*)d_in[4];
    const float* W_out   = (const float*)d_in[5];
    const float* A       = (const float*)d_in[6];
    float* out = (float*)d_out;

    // 1) in_proj + split + silu(z)
    gemm_kernel<0><<<dim3(8, 32), 128>>>(x, W_in, nullptr, nullptr, nullptr);
    // 2) delta / bu / Cv projections (fused triple GEMM)
    gemm_kernel<1><<<dim3(12, 32), 128>>>(nullptr, W_delta, W_B, W_C, nullptr);
    // 3) selective scan (+ * silu(z))
    scan_kernel<<<256, 128>>>(A);
    // 4) out_proj
    gemm_kernel<2><<<dim3(2, 32), 128>>>(nullptr, W_out, nullptr, nullptr, out);
}

// round 2
// speedup vs baseline: 1.6833x; 1.6833x over previous
#include <cuda_runtime.h>
#include <cuda_bf16.h>

// Problem constants
#define BATCH   4
#define LENGTH  512
#define DMODEL  128
#define DINNER  256
#define DSTATE  256
#define MROWS   (BATCH * LENGTH)        // 2048
#define LOG2E   1.4426950408889634f
#define NC      8                       // scan chunks
#define TC      64                      // steps per chunk (NC*TC == LENGTH)

// Scratch (allocation-free: __device__ globals)
__device__ float g_xs[MROWS * DINNER];     // xs (first half of in_proj)
__device__ float g_sz[MROWS * DINNER];     // silu(z)
__device__ float g_delta[MROWS * DINNER];  // xs @ W_delta
__device__ float g_bu[MROWS * DSTATE];     // (xs @ W_B) * xs   (elementwise)
__device__ float g_Cv[MROWS * DINNER];     // xs @ W_C
__device__ float g_y[MROWS * DINNER];      // scan output * silu(z)

// Chunked-scan intermediates: layout [((b*NC + c)*256 + d)*256 + n]
__device__ float g_P  [BATCH * NC * DINNER * DSTATE];  // per-chunk prod of a_t
__device__ float g_Sf [BATCH * NC * DINNER * DSTATE];  // per-chunk local final state
__device__ float g_Sin[BATCH * NC * DINNER * DSTATE];  // per-chunk initial state

// ---------------------------------------------------------------------------
// Tiled fp32 GEMM: C[64x64] per block, 128 threads, thread tile 8x4.
// MODE 0: x(2048x128) @ W_in(128x512)  -> split: xs | silu(z)
// MODE 1: g_xs(2048x256) @ {W_delta,W_B,W_C}(256x256) -> delta | bu | Cv
// MODE 2: g_y(2048x256) @ W_out(256x128) -> d_out
// ---------------------------------------------------------------------------
template <int MODE>
__global__ __launch_bounds__(128)
void gemm_kernel(const float* __restrict__ Ag_,
                 const float* __restrict__ B0,
                 const float* __restrict__ B1,
                 const float* __restrict__ B2,
                 float* __restrict__ Og)
{
    constexpr int K   = (MODE == 0) ? 128 : 256;
    constexpr int LDB = (MODE == 0) ? 512 : ((MODE == 1) ? 256 : 128);

    __shared__ float As[16][68];
    __shared__ float Bs[16][68];

    const int tid = threadIdx.x;
    const int tx  = tid & 15;
    const int ty  = tid >> 4;
    const int m0  = blockIdx.y * 64;

    const float* Ag;
    const float* Bg;
    int n0;
    int which = 0;
    if (MODE == 1) {
        which = blockIdx.x >> 2;              // 0: W_delta, 1: W_B, 2: W_C
        n0 = (blockIdx.x & 3) * 64;
        Bg = (which == 0) ? B0 : ((which == 1) ? B1 : B2);
        Ag = g_xs;
    } else {
        n0 = blockIdx.x * 64;
        Bg = B0;
        Ag = (MODE == 0) ? Ag_ : g_y;
    }

    float acc[8][4];
#pragma unroll
    for (int i = 0; i < 8; i++)
#pragma unroll
        for (int j = 0; j < 4; j++) acc[i][j] = 0.f;

    for (int k0 = 0; k0 < K; k0 += 16) {
#pragma unroll
        for (int r = 0; r < 2; r++) {
            int idx = tid + r * 128;
            int row = idx >> 2;
            int c4  = (idx & 3) << 2;
            float4 v = *(const float4*)(Ag + (size_t)(m0 + row) * K + k0 + c4);
            As[c4 + 0][row] = v.x;
            As[c4 + 1][row] = v.y;
            As[c4 + 2][row] = v.z;
            As[c4 + 3][row] = v.w;
        }
#pragma unroll
        for (int r = 0; r < 2; r++) {
            int idx  = tid + r * 128;
            int rowk = idx >> 4;
            int c4   = (idx & 15) << 2;
            *(float4*)&Bs[rowk][c4] =
                *(const float4*)(Bg + (size_t)(k0 + rowk) * LDB + n0 + c4);
        }
        __syncthreads();

#pragma unroll
        for (int kk = 0; kk < 16; kk++) {
            float4 a0 = *(const float4*)&As[kk][ty * 8];
            float4 a1 = *(const float4*)&As[kk][ty * 8 + 4];
            float4 bb = *(const float4*)&Bs[kk][tx * 4];
            float a[8] = {a0.x, a0.y, a0.z, a0.w, a1.x, a1.y, a1.z, a1.w};
            float bv[4] = {bb.x, bb.y, bb.z, bb.w};
#pragma unroll
            for (int i = 0; i < 8; i++)
#pragma unroll
                for (int j = 0; j < 4; j++)
                    acc[i][j] = fmaf(a[i], bv[j], acc[i][j]);
        }
        __syncthreads();
    }

#pragma unroll
    for (int i = 0; i < 8; i++) {
        int m = m0 + ty * 8 + i;
#pragma unroll
        for (int j = 0; j < 4; j++) {
            int c = n0 + tx * 4 + j;
            float v = acc[i][j];
            if (MODE == 0) {
                if (c < 256) {
                    g_xs[m * 256 + c] = v;
                } else {
                    float sig = 1.f / (1.f + __expf(-v));
                    g_sz[m * 256 + (c - 256)] = v * sig;   // silu(z)
                }
            } else if (MODE == 1) {
                if (which == 0)      g_delta[m * 256 + c] = v;
                else if (which == 1) g_bu[m * 256 + c] = v * g_xs[m * 256 + c];
                else                 g_Cv[m * 256 + c] = v;
            } else {
                Og[m * 128 + c] = v;
            }
        }
    }
}

// ---------------------------------------------------------------------------
// Chunked selective scan, pass 1: chunks 0..NC-2 compute, per (b,c,d,n):
//   P  = prod_{t in chunk} exp(delta_t * A)
//   Sf = local final state (zero-initialized recurrence)
// One warp per (b,c,d); lane owns 8 contiguous n's.
// High occupancy (7168 warps) makes this latency-tolerant: no prefetch needed.
// ---------------------------------------------------------------------------
__global__ __launch_bounds__(128)
void scan_p1(const float* __restrict__ A)
{
    const int warp = threadIdx.x >> 5;
    const int lane = threadIdx.x & 31;
    int bid = blockIdx.x;                  // ((c*BATCH + b)*64 + dblk)
    const int dblk = bid & 63;  bid >>= 6;
    const int b    = bid & 3;   bid >>= 2;
    const int c    = bid;                  // 0 .. NC-2
    const int d    = (dblk << 2) | warp;
    const int nb   = lane << 3;

    float Ae[8];
#pragma unroll
    for (int j = 0; j < 8; j++)
        Ae[j] = A[d * 256 + nb + j] * LOG2E;

    const int base = b * LENGTH * 256;
    const float* __restrict__ bu = g_bu    + base;
    const float* __restrict__ dp = g_delta + base;

    float s[8], P[8];
#pragma unroll
    for (int j = 0; j < 8; j++) { s[j] = 0.f; P[j] = 1.f; }

    const int t0 = c * TC;
    for (int t = t0; t < t0 + TC; t++) {
        const float delta = dp[t * 256 + d];
        float buv[8];
        *(float4*)&buv[0] = *(const float4*)(bu + t * 256 + nb);
        *(float4*)&buv[4] = *(const float4*)(bu + t * 256 + nb + 4);
#pragma unroll
        for (int j = 0; j < 8; j++) {
            float p = delta * Ae[j];
            float e;
            asm("ex2.approx.ftz.f32 %0, %1;" : "=f"(e) : "f"(p));
            P[j] *= e;
            s[j] = fmaf(e, s[j], delta * buv[j]);
        }
    }

    const size_t o = ((size_t)((b * NC + c) * 256 + d)) * 256 + nb;
    *(float4*)(g_P  + o)     = *(float4*)&P[0];
    *(float4*)(g_P  + o + 4) = *(float4*)&P[4];
    *(float4*)(g_Sf + o)     = *(float4*)&s[0];
    *(float4*)(g_Sf + o + 4) = *(float4*)&s[4];
}

// ---------------------------------------------------------------------------
// Chunk-summary scan: per (b,d,n) element, 7 sequential chunk steps:
//   Sin[c+1] = P[c] * Sin[c] + Sf[c],   Sin[0] = 0
// Fully coalesced over n. 262144 threads.
// ---------------------------------------------------------------------------
__global__ __launch_bounds__(256)
void chunk_scan()
{
    const int i  = blockIdx.x * 256 + threadIdx.x;   // (b*65536 + d*256 + n)
    const int b  = i >> 16;
    const int dn = i & 65535;

    float S = 0.f;
#pragma unroll
    for (int c = 0; c < NC - 1; c++) {
        const size_t o = ((size_t)(b * NC + c) << 16) + dn;
        S = fmaf(g_P[o], S, g_Sf[o]);
        g_Sin[o + 65536] = S;   // slot c+1
    }
}

// ---------------------------------------------------------------------------
// Pass 2: all NC chunks in parallel, recurrence initialized with Sin[c],
// computes y[b,t,d] = (sum_n s*C) * silu(z). One warp per (b,c,d).
// ---------------------------------------------------------------------------
__global__ __launch_bounds__(128)
void scan_p2(const float* __restrict__ A)
{
    const int warp = threadIdx.x >> 5;
    const int lane = threadIdx.x & 31;
    int bid = blockIdx.x;                  // ((c*BATCH + b)*64 + dblk)
    const int dblk = bid & 63;  bid >>= 6;
    const int b    = bid & 3;   bid >>= 2;
    const int c    = bid;                  // 0 .. NC-1
    const int d    = (dblk << 2) | warp;
    const int nb   = lane << 3;

    float Ae[8];
#pragma unroll
    for (int j = 0; j < 8; j++)
        Ae[j] = A[d * 256 + nb + j] * LOG2E;

    const int base = b * LENGTH * 256;
    const float* __restrict__ bu  = g_bu    + base;
    const float* __restrict__ Cp  = g_Cv    + base;
    const float* __restrict__ dp  = g_delta + base;
    const float* __restrict__ szp = g_sz    + base;
    float*       __restrict__ yp  = g_y     + base;

    float s[8];
    if (c == 0) {
#pragma unroll
        for (int j = 0; j < 8; j++) s[j] = 0.f;
    } else {
        const size_t o = ((size_t)((b * NC + c) * 256 + d)) * 256 + nb;
        *(float4*)&s[0] = *(const float4*)(g_Sin + o);
        *(float4*)&s[4] = *(const float4*)(g_Sin + o + 4);
    }

    const int t0 = c * TC;
    for (int t = t0; t < t0 + TC; t++) {
        const float delta = dp[t * 256 + d];
        float buv[8], cv[8];
        *(float4*)&buv[0] = *(const float4*)(bu + t * 256 + nb);
        *(float4*)&buv[4] = *(const float4*)(bu + t * 256 + nb + 4);
        *(float4*)&cv[0]  = *(const float4*)(Cp + t * 256 + nb);
        *(float4*)&cv[4]  = *(const float4*)(Cp + t * 256 + nb + 4);

        float yacc = 0.f;
#pragma unroll
        for (int j = 0; j < 8; j++) {
            float p = delta * Ae[j];
            float e;
            asm("ex2.approx.ftz.f32 %0, %1;" : "=f"(e) : "f"(p));
            s[j] = fmaf(e, s[j], delta * buv[j]);
            yacc = fmaf(s[j], cv[j], yacc);
        }
        yacc += __shfl_xor_sync(0xffffffffu, yacc, 16);
        yacc += __shfl_xor_sync(0xffffffffu, yacc, 8);
        yacc += __shfl_xor_sync(0xffffffffu, yacc, 4);
        yacc += __shfl_xor_sync(0xffffffffu, yacc, 2);
        yacc += __shfl_xor_sync(0xffffffffu, yacc, 1);
        if (lane == 0)
            yp[t * 256 + d] = yacc * szp[t * 256 + d];
    }
}

// ---------------------------------------------------------------------------
// Inputs (metadata order): x, W_in, W_delta, W_B, W_C, W_out, A, D(unused)
// ---------------------------------------------------------------------------
extern "C" void kernel_launch(void* const* d_in, const int* in_sizes, int n_in,
                              void* d_out, int out_size)
{
    const float* x       = (const float*)d_in[0];
    const float* W_in    = (const float*)d_in[1];
    const float* W_delta = (const float*)d_in[2];
    const float* W_B     = (const float*)d_in[3];
    const float* W_C     = (const float*)d_in[4];
    const float* W_out   = (const float*)d_in[5];
    const float* A       = (const float*)d_in[6];
    float* out = (float*)d_out;

    // 1) in_proj + split + silu(z)
    gemm_kernel<0><<<dim3(8, 32), 128>>>(x, W_in, nullptr, nullptr, nullptr);
    // 2) delta / bu / Cv projections (fused triple GEMM)
    gemm_kernel<1><<<dim3(12, 32), 128>>>(nullptr, W_delta, W_B, W_C, nullptr);
    // 3) chunked selective scan: pass1 (chunks 0..6), chunk summary scan, pass2
    scan_p1<<<(NC - 1) * BATCH * 64, 128>>>(A);
    chunk_scan<<<(BATCH * DINNER * DSTATE) / 256, 256>>>();
    scan_p2<<<NC * BATCH * 64, 128>>>(A);
    // 4) out_proj
    gemm_kernel<2><<<dim3(2, 32), 128>>>(nullptr, W_out, nullptr, nullptr, out);
}

// round 3
// speedup vs baseline: 1.7300x; 1.0278x over previous
#include <cuda_runtime.h>
#include <cuda_bf16.h>

// Problem constants
#define BATCH   4
#define LENGTH  512
#define DMODEL  128
#define DINNER  256
#define DSTATE  256
#define MROWS   (BATCH * LENGTH)        // 2048
#define LOG2E   1.4426950408889634f
#define NC      8                       // scan chunks
#define TC      64                      // steps per chunk (NC*TC == LENGTH)

// Scratch (allocation-free: __device__ globals)
__device__ float g_xs[MROWS * DINNER];     // xs (first half of in_proj)
__device__ float g_sz[MROWS * DINNER];     // silu(z)
__device__ float g_delta[MROWS * DINNER];  // xs @ W_delta
__device__ float g_bu[MROWS * DSTATE];     // (xs @ W_B) * xs   (elementwise)
__device__ float g_Cv[MROWS * DINNER];     // xs @ W_C
__device__ float g_y[MROWS * DINNER];      // scan output * silu(z)

// Chunked-scan intermediates: layout [((b*NC + c)*256 + d)*256 + n]
__device__ float g_P  [BATCH * NC * DINNER * DSTATE];  // per-chunk prod of a_t
__device__ float g_Sf [BATCH * NC * DINNER * DSTATE];  // per-chunk local final state
__device__ float g_Sin[BATCH * NC * DINNER * DSTATE];  // per-chunk initial state

// ---------------------------------------------------------------------------
// Tiled fp32 GEMM with register double-buffering: C[64x64] per block,
// 128 threads, thread tile 8x4. Next K-tile's global loads are issued right
// after the store-phase sync, overlapping the ~250-600cyc L2/DRAM latency
// with the 16-step FFMA compute phase.
// MODE 0: x(2048x128) @ W_in(128x512)  -> split: xs | silu(z)
// MODE 1: g_xs(2048x256) @ {W_delta,W_B,W_C}(256x256) -> delta | bu | Cv
// MODE 2: g_y(2048x256) @ W_out(256x128) -> d_out
// ---------------------------------------------------------------------------
template <int MODE>
__global__ __launch_bounds__(128)
void gemm_kernel(const float* __restrict__ Ag_,
                 const float* __restrict__ B0,
                 const float* __restrict__ B1,
                 const float* __restrict__ B2,
                 float* __restrict__ Og)
{
    constexpr int K   = (MODE == 0) ? 128 : 256;
    constexpr int LDB = (MODE == 0) ? 512 : ((MODE == 1) ? 256 : 128);

    __shared__ float As[16][68];
    __shared__ float Bs[16][68];

    const int tid = threadIdx.x;
    const int tx  = tid & 15;
    const int ty  = tid >> 4;
    const int m0  = blockIdx.y * 64;

    const float* Ag;
    const float* Bg;
    int n0;
    int which = 0;
    if (MODE == 1) {
        which = blockIdx.x >> 2;              // 0: W_delta, 1: W_B, 2: W_C
        n0 = (blockIdx.x & 3) * 64;
        Bg = (which == 0) ? B0 : ((which == 1) ? B1 : B2);
        Ag = g_xs;
    } else {
        n0 = blockIdx.x * 64;
        Bg = B0;
        Ag = (MODE == 0) ? Ag_ : g_y;
    }

    // Per-thread load slots (2 float4 each for A and B tile)
    const int aRow0 = tid >> 2;            // A: row within 64, thread covers 2 rows (stride 32... via idx)
    const int aC4   = (tid & 3) << 2;      // A: k-subcolumn (0,4,8,12)
    const int bRowk0 = tid >> 4;           // B: k-row within 16 (thread covers 2, stride 8)
    const int bC4   = (tid & 15) << 2;     // B: n-subcolumn

    float4 aR[2], bR[2];
#pragma unroll
    for (int r = 0; r < 2; r++) {
        aR[r] = *(const float4*)(Ag + (size_t)(m0 + aRow0 + r * 32) * K + aC4);
        bR[r] = *(const float4*)(Bg + (size_t)(bRowk0 + r * 8) * LDB + n0 + bC4);
    }

    float acc[8][4];
#pragma unroll
    for (int i = 0; i < 8; i++)
#pragma unroll
        for (int j = 0; j < 4; j++) acc[i][j] = 0.f;

    for (int k0 = 0; k0 < K; k0 += 16) {
        // stage registers -> smem (A transposed)
#pragma unroll
        for (int r = 0; r < 2; r++) {
            int row = aRow0 + r * 32;
            As[aC4 + 0][row] = aR[r].x;
            As[aC4 + 1][row] = aR[r].y;
            As[aC4 + 2][row] = aR[r].z;
            As[aC4 + 3][row] = aR[r].w;
            *(float4*)&Bs[bRowk0 + r * 8][bC4] = bR[r];
        }
        __syncthreads();

        // issue next tile's loads (latency overlapped with compute below)
        if (k0 + 16 < K) {
#pragma unroll
            for (int r = 0; r < 2; r++) {
                aR[r] = *(const float4*)(Ag + (size_t)(m0 + aRow0 + r * 32) * K + (k0 + 16) + aC4);
                bR[r] = *(const float4*)(Bg + (size_t)(k0 + 16 + bRowk0 + r * 8) * LDB + n0 + bC4);
            }
        }

#pragma unroll
        for (int kk = 0; kk < 16; kk++) {
            float4 a0 = *(const float4*)&As[kk][ty * 8];
            float4 a1 = *(const float4*)&As[kk][ty * 8 + 4];
            float4 bb = *(const float4*)&Bs[kk][tx * 4];
            float a[8] = {a0.x, a0.y, a0.z, a0.w, a1.x, a1.y, a1.z, a1.w};
            float bv[4] = {bb.x, bb.y, bb.z, bb.w};
#pragma unroll
            for (int i = 0; i < 8; i++)
#pragma unroll
                for (int j = 0; j < 4; j++)
                    acc[i][j] = fmaf(a[i], bv[j], acc[i][j]);
        }
        __syncthreads();
    }

#pragma unroll
    for (int i = 0; i < 8; i++) {
        int m = m0 + ty * 8 + i;
#pragma unroll
        for (int j = 0; j < 4; j++) {
            int c = n0 + tx * 4 + j;
            float v = acc[i][j];
            if (MODE == 0) {
                if (c < 256) {
                    g_xs[m * 256 + c] = v;
                } else {
                    float sig = 1.f / (1.f + __expf(-v));
                    g_sz[m * 256 + (c - 256)] = v * sig;   // silu(z)
                }
            } else if (MODE == 1) {
                if (which == 0)      g_delta[m * 256 + c] = v;
                else if (which == 1) g_bu[m * 256 + c] = v * g_xs[m * 256 + c];
                else                 g_Cv[m * 256 + c] = v;
            } else {
                Og[m * 128 + c] = v;
            }
        }
    }
}

// ---------------------------------------------------------------------------
// Chunked selective scan, pass 1: chunks 0..NC-2 compute, per (b,c,d,n):
//   P  = prod_{t in chunk} exp(delta_t * A)
//   Sf = local final state (zero-initialized recurrence)
// One warp per (b,c,d); lane owns 8 contiguous n's.
// ---------------------------------------------------------------------------
__global__ __launch_bounds__(128)
void scan_p1(const float* __restrict__ A)
{
    const int warp = threadIdx.x >> 5;
    const int lane = threadIdx.x & 31;
    int bid = blockIdx.x;                  // ((c*BATCH + b)*64 + dblk)
    const int dblk = bid & 63;  bid >>= 6;
    const int b    = bid & 3;   bid >>= 2;
    const int c    = bid;                  // 0 .. NC-2
    const int d    = (dblk << 2) | warp;
    const int nb   = lane << 3;

    float Ae[8];
#pragma unroll
    for (int j = 0; j < 8; j++)
        Ae[j] = A[d * 256 + nb + j] * LOG2E;

    const int base = b * LENGTH * 256;
    const float* __restrict__ bu = g_bu    + base;
    const float* __restrict__ dp = g_delta + base;

    float s[8], P[8];
#pragma unroll
    for (int j = 0; j < 8; j++) { s[j] = 0.f; P[j] = 1.f; }

    const int t0 = c * TC;
    for (int t = t0; t < t0 + TC; t++) {
        const float delta = dp[t * 256 + d];
        float buv[8];
        *(float4*)&buv[0] = *(const float4*)(bu + t * 256 + nb);
        *(float4*)&buv[4] = *(const float4*)(bu + t * 256 + nb + 4);
#pragma unroll
        for (int j = 0; j < 8; j++) {
            float p = delta * Ae[j];
            float e;
            asm("ex2.approx.ftz.f32 %0, %1;" : "=f"(e) : "f"(p));
            P[j] *= e;
            s[j] = fmaf(e, s[j], delta * buv[j]);
        }
    }

    const size_t o = ((size_t)((b * NC + c) * 256 + d)) * 256 + nb;
    *(float4*)(g_P  + o)     = *(float4*)&P[0];
    *(float4*)(g_P  + o + 4) = *(float4*)&P[4];
    *(float4*)(g_Sf + o)     = *(float4*)&s[0];
    *(float4*)(g_Sf + o + 4) = *(float4*)&s[4];
}

// ---------------------------------------------------------------------------
// Chunk-summary scan, float4-vectorized: per (b,d,n4), 7 sequential steps:
//   Sin[c+1] = P[c] * Sin[c] + Sf[c],   Sin[0] = 0
// 65536 threads, 4 elements each, fully coalesced.
// ---------------------------------------------------------------------------
__global__ __launch_bounds__(256)
void chunk_scan()
{
    const int i   = blockIdx.x * 256 + threadIdx.x;   // float4 index
    const int b   = i >> 14;                          // 16384 float4 per batch
    const int dn4 = i & 16383;

    float4 S = make_float4(0.f, 0.f, 0.f, 0.f);
#pragma unroll
    for (int c = 0; c < NC - 1; c++) {
        const size_t o4 = ((size_t)(b * NC + c) << 14) + dn4;
        float4 P  = ((const float4*)g_P )[o4];
        float4 Sf = ((const float4*)g_Sf)[o4];
        S.x = fmaf(P.x, S.x, Sf.x);
        S.y = fmaf(P.y, S.y, Sf.y);
        S.z = fmaf(P.z, S.z, Sf.z);
        S.w = fmaf(P.w, S.w, Sf.w);
        ((float4*)g_Sin)[o4 + 16384] = S;   // slot c+1
    }
}

// ---------------------------------------------------------------------------
// Pass 2: all NC chunks in parallel, recurrence initialized with Sin[c],
// computes y[b,t,d] = (sum_n s*C) * silu(z). One warp per (b,c,d).
// ---------------------------------------------------------------------------
__global__ __launch_bounds__(128)
void scan_p2(const float* __restrict__ A)
{
    const int warp = threadIdx.x >> 5;
    const int lane = threadIdx.x & 31;
    int bid = blockIdx.x;                  // ((c*BATCH + b)*64 + dblk)
    const int dblk = bid & 63;  bid >>= 6;
    const int b    = bid & 3;   bid >>= 2;
    const int c    = bid;                  // 0 .. NC-1
    const int d    = (dblk << 2) | warp;
    const int nb   = lane << 3;

    float Ae[8];
#pragma unroll
    for (int j = 0; j < 8; j++)
        Ae[j] = A[d * 256 + nb + j] * LOG2E;

    const int base = b * LENGTH * 256;
    const float* __restrict__ bu  = g_bu    + base;
    const float* __restrict__ Cp  = g_Cv    + base;
    const float* __restrict__ dp  = g_delta + base;
    const float* __restrict__ szp = g_sz    + base;
    float*       __restrict__ yp  = g_y     + base;

    float s[8];
    if (c == 0) {
#pragma unroll
        for (int j = 0; j < 8; j++) s[j] = 0.f;
    } else {
        const size_t o = ((size_t)((b * NC + c) * 256 + d)) * 256 + nb;
        *(float4*)&s[0] = *(const float4*)(g_Sin + o);
        *(float4*)&s[4] = *(const float4*)(g_Sin + o + 4);
    }

    const int t0 = c * TC;
    for (int t = t0; t < t0 + TC; t++) {
        const float delta = dp[t * 256 + d];
        float buv[8], cv[8];
        *(float4*)&buv[0] = *(const float4*)(bu + t * 256 + nb);
        *(float4*)&buv[4] = *(const float4*)(bu + t * 256 + nb + 4);
        *(float4*)&cv[0]  = *(const float4*)(Cp + t * 256 + nb);
        *(float4*)&cv[4]  = *(const float4*)(Cp + t * 256 + nb + 4);

        float yacc = 0.f;
#pragma unroll
        for (int j = 0; j < 8; j++) {
            float p = delta * Ae[j];
            float e;
            asm("ex2.approx.ftz.f32 %0, %1;" : "=f"(e) : "f"(p));
            s[j] = fmaf(e, s[j], delta * buv[j]);
            yacc = fmaf(s[j], cv[j], yacc);
        }
        yacc += __shfl_xor_sync(0xffffffffu, yacc, 16);
        yacc += __shfl_xor_sync(0xffffffffu, yacc, 8);
        yacc += __shfl_xor_sync(0xffffffffu, yacc, 4);
        yacc += __shfl_xor_sync(0xffffffffu, yacc, 2);
        yacc += __shfl_xor_sync(0xffffffffu, yacc, 1);
        if (lane == 0)
            yp[t * 256 + d] = yacc * szp[t * 256 + d];
    }
}

// ---------------------------------------------------------------------------
// Inputs (metadata order): x, W_in, W_delta, W_B, W_C, W_out, A, D(unused)
// ---------------------------------------------------------------------------
extern "C" void kernel_launch(void* const* d_in, const int* in_sizes, int n_in,
                              void* d_out, int out_size)
{
    const float* x       = (const float*)d_in[0];
    const float* W_in    = (const float*)d_in[1];
    const float* W_delta = (const float*)d_in[2];
    const float* W_B     = (const float*)d_in[3];
    const float* W_C     = (const float*)d_in[4];
    const float* W_out   = (const float*)d_in[5];
    const float* A       = (const float*)d_in[6];
    float* out = (float*)d_out;

    // 1) in_proj + split + silu(z)
    gemm_kernel<0><<<dim3(8, 32), 128>>>(x, W_in, nullptr, nullptr, nullptr);
    // 2) delta / bu / Cv projections (fused triple GEMM)
    gemm_kernel<1><<<dim3(12, 32), 128>>>(nullptr, W_delta, W_B, W_C, nullptr);
    // 3) chunked selective scan: pass1 (chunks 0..6), chunk summary scan, pass2
    scan_p1<<<(NC - 1) * BATCH * 64, 128>>>(A);
    chunk_scan<<<(BATCH * DINNER * DSTATE) / 1024, 256>>>();
    scan_p2<<<NC * BATCH * 64, 128>>>(A);
    // 4) out_proj
    gemm_kernel<2><<<dim3(2, 32), 128>>>(nullptr, W_out, nullptr, nullptr, out);
}

// round 5
// speedup vs baseline: 1.8507x; 1.0698x over previous
#include <cuda_runtime.h>
#include <cuda_bf16.h>

// Problem constants
#define BATCH   4
#define LENGTH  512
#define DMODEL  128
#define DINNER  256
#define DSTATE  256
#define MROWS   (BATCH * LENGTH)        // 2048
#define LOG2E   1.4426950408889634f
#define NC      8                       // scan chunks
#define TC      64                      // steps per chunk (NC*TC == LENGTH)

// Scratch (allocation-free: __device__ globals)
__device__ float g_xs[MROWS * DINNER];     // xs (first half of in_proj)
__device__ float g_sz[MROWS * DINNER];     // silu(z)
__device__ float g_delta[MROWS * DINNER];  // xs @ W_delta
__device__ float g_bu[MROWS * DSTATE];     // (xs @ W_B) * xs   (elementwise)
__device__ float g_Cv[MROWS * DINNER];     // xs @ W_C
__device__ float g_y[MROWS * DINNER];      // scan output * silu(z)

// Chunked-scan intermediates: layout [((b*NC + c)*256 + d)*256 + n]
__device__ float g_P  [BATCH * NC * DINNER * DSTATE];  // per-chunk prod of a_t
__device__ float g_Sf [BATCH * NC * DINNER * DSTATE];  // per-chunk local final state

// ---------------------------------------------------------------------------
// Tiled fp32 GEMM: C tile 32x64 per block, 128 threads, thread tile 4x4.
// Small tiles -> 2x the blocks of the old 64x64 version: every SM gets work
// (FFMA rt_SMSP=2 means issue is parallelism-bound, not latency-bound).
// Register double-buffering of the next K-tile retained.
// MODE 0: x(2048x128) @ W_in(128x512)  -> split: xs | silu(z)
// MODE 1: g_xs(2048x256) @ {W_delta,W_B,W_C}(256x256) -> delta | bu | Cv
// MODE 2: g_y(2048x256) @ W_out(256x128) -> d_out
// ---------------------------------------------------------------------------
template <int MODE>
__global__ __launch_bounds__(128)
void gemm_kernel(const float* __restrict__ Ag_,
                 const float* __restrict__ B0,
                 const float* __restrict__ B1,
                 const float* __restrict__ B2,
                 float* __restrict__ Og)
{
    constexpr int K   = (MODE == 0) ? 128 : 256;
    constexpr int LDB = (MODE == 0) ? 512 : ((MODE == 1) ? 256 : 128);

    __shared__ float As[16][36];   // transposed A tile [k][m], m=32 (+pad)
    __shared__ float Bs[16][68];   // B tile [k][n], n=64 (+pad)

    const int tid = threadIdx.x;
    const int tx  = tid & 15;      // n group (4 cols each)
    const int ty  = tid >> 4;      // m group (4 rows each), 0..7
    const int m0  = blockIdx.y * 32;

    const float* Ag;
    const float* Bg;
    int n0;
    int which = 0;
    if (MODE == 1) {
        which = blockIdx.x >> 2;              // 0: W_delta, 1: W_B, 2: W_C
        n0 = (blockIdx.x & 3) * 64;
        Bg = (which == 0) ? B0 : ((which == 1) ? B1 : B2);
        Ag = g_xs;
    } else {
        n0 = blockIdx.x * 64;
        Bg = B0;
        Ag = (MODE == 0) ? Ag_ : g_y;
    }

    // Per-thread load slots: A = 1 float4 (32x16 tile), B = 2 float4 (16x64)
    const int aRow  = tid >> 2;            // 0..31
    const int aC4   = (tid & 3) << 2;      // 0,4,8,12
    const int bRowk = tid >> 4;            // 0..7 (2 rounds, +8)
    const int bC4   = (tid & 15) << 2;     // 0..60

    float4 aR;
    float4 bR[2];
    aR = *(const float4*)(Ag + (size_t)(m0 + aRow) * K + aC4);
#pragma unroll
    for (int r = 0; r < 2; r++)
        bR[r] = *(const float4*)(Bg + (size_t)(bRowk + r * 8) * LDB + n0 + bC4);

    float acc[4][4];
#pragma unroll
    for (int i = 0; i < 4; i++)
#pragma unroll
        for (int j = 0; j < 4; j++) acc[i][j] = 0.f;

    for (int k0 = 0; k0 < K; k0 += 16) {
        // stage registers -> smem (A transposed)
        As[aC4 + 0][aRow] = aR.x;
        As[aC4 + 1][aRow] = aR.y;
        As[aC4 + 2][aRow] = aR.z;
        As[aC4 + 3][aRow] = aR.w;
#pragma unroll
        for (int r = 0; r < 2; r++)
            *(float4*)&Bs[bRowk + r * 8][bC4] = bR[r];
        __syncthreads();

        // issue next K-tile's loads (overlapped with compute)
        if (k0 + 16 < K) {
            aR = *(const float4*)(Ag + (size_t)(m0 + aRow) * K + (k0 + 16) + aC4);
#pragma unroll
            for (int r = 0; r < 2; r++)
                bR[r] = *(const float4*)(Bg + (size_t)(k0 + 16 + bRowk + r * 8) * LDB + n0 + bC4);
        }

#pragma unroll
        for (int kk = 0; kk < 16; kk++) {
            float4 av = *(const float4*)&As[kk][ty * 4];
            float4 bv = *(const float4*)&Bs[kk][tx * 4];
            float a[4] = {av.x, av.y, av.z, av.w};
            float b[4] = {bv.x, bv.y, bv.z, bv.w};
#pragma unroll
            for (int i = 0; i < 4; i++)
#pragma unroll
                for (int j = 0; j < 4; j++)
                    acc[i][j] = fmaf(a[i], b[j], acc[i][j]);
        }
        __syncthreads();
    }

#pragma unroll
    for (int i = 0; i < 4; i++) {
        int m = m0 + ty * 4 + i;
#pragma unroll
        for (int j = 0; j < 4; j++) {
            int c = n0 + tx * 4 + j;
            float v = acc[i][j];
            if (MODE == 0) {
                if (c < 256) {
                    g_xs[m * 256 + c] = v;
                } else {
                    float sig = 1.f / (1.f + __expf(-v));
                    g_sz[m * 256 + (c - 256)] = v * sig;   // silu(z)
                }
            } else if (MODE == 1) {
                if (which == 0)      g_delta[m * 256 + c] = v;
                else if (which == 1) g_bu[m * 256 + c] = v * g_xs[m * 256 + c];
                else                 g_Cv[m * 256 + c] = v;
            } else {
                Og[m * 128 + c] = v;
            }
        }
    }
}

// ---------------------------------------------------------------------------
// Chunked selective scan, pass 1: chunks 0..NC-2 compute, per (b,c,d,n):
//   P  = prod_{t in chunk} exp(delta_t * A)
//   Sf = local final state (zero-initialized recurrence)
// One warp per (b,c,d); lane owns 8 contiguous n's.
// ---------------------------------------------------------------------------
__global__ __launch_bounds__(128)
void scan_p1(const float* __restrict__ A)
{
    const int warp = threadIdx.x >> 5;
    const int lane = threadIdx.x & 31;
    int bid = blockIdx.x;                  // ((c*BATCH + b)*64 + dblk)
    const int dblk = bid & 63;  bid >>= 6;
    const int b    = bid & 3;   bid >>= 2;
    const int c    = bid;                  // 0 .. NC-2
    const int d    = (dblk << 2) | warp;
    const int nb   = lane << 3;

    float Ae[8];
#pragma unroll
    for (int j = 0; j < 8; j++)
        Ae[j] = A[d * 256 + nb + j] * LOG2E;

    const int base = b * LENGTH * 256;
    const float* __restrict__ bu = g_bu    + base;
    const float* __restrict__ dp = g_delta + base;

    float s[8], P[8];
#pragma unroll
    for (int j = 0; j < 8; j++) { s[j] = 0.f; P[j] = 1.f; }

    const int t0 = c * TC;
    for (int t = t0; t < t0 + TC; t++) {
        const float delta = dp[t * 256 + d];
        float buv[8];
        *(float4*)&buv[0] = *(const float4*)(bu + t * 256 + nb);
        *(float4*)&buv[4] = *(const float4*)(bu + t * 256 + nb + 4);
#pragma unroll
        for (int j = 0; j < 8; j++) {
            float p = delta * Ae[j];
            float e;
            asm("ex2.approx.ftz.f32 %0, %1;" : "=f"(e) : "f"(p));
            P[j] *= e;
            s[j] = fmaf(e, s[j], delta * buv[j]);
        }
    }

    const size_t o = ((size_t)((b * NC + c) * 256 + d)) * 256 + nb;
    *(float4*)(g_P  + o)     = *(float4*)&P[0];
    *(float4*)(g_P  + o + 4) = *(float4*)&P[4];
    *(float4*)(g_Sf + o)     = *(float4*)&s[0];
    *(float4*)(g_Sf + o + 4) = *(float4*)&s[4];
}

// ---------------------------------------------------------------------------
// Pass 2 (with fused chunk-summary scan): each warp first reconstructs its
// chunk's initial state from the <=7 preceding chunks' (P, Sf) pairs
// (short dependent chain, L2-resident, overlapped across 2048 warps), then
// runs the recurrence producing y[b,t,d] = (sum_n s*C) * silu(z).
// ---------------------------------------------------------------------------
__global__ __launch_bounds__(128)
void scan_p2(const float* __restrict__ A)
{
    const int warp = threadIdx.x >> 5;
    const int lane = threadIdx.x & 31;
    int bid = blockIdx.x;                  // ((c*BATCH + b)*64 + dblk)
    const int dblk = bid & 63;  bid >>= 6;
    const int b    = bid & 3;   bid >>= 2;
    const int c    = bid;                  // 0 .. NC-1
    const int d    = (dblk << 2) | warp;
    const int nb   = lane << 3;

    float Ae[8];
#pragma unroll
    for (int j = 0; j < 8; j++)
        Ae[j] = A[d * 256 + nb + j] * LOG2E;

    // Reconstruct initial state: Sin = scan over chunks 0..c-1 of (P, Sf)
    float s[8];
#pragma unroll
    for (int j = 0; j < 8; j++) s[j] = 0.f;
    for (int cc = 0; cc < c; cc++) {
        const size_t o = ((size_t)((b * NC + cc) * 256 + d)) * 256 + nb;
        float P[8], Sf[8];
        *(float4*)&P[0]  = *(const float4*)(g_P  + o);
        *(float4*)&P[4]  = *(const float4*)(g_P  + o + 4);
        *(float4*)&Sf[0] = *(const float4*)(g_Sf + o);
        *(float4*)&Sf[4] = *(const float4*)(g_Sf + o + 4);
#pragma unroll
        for (int j = 0; j < 8; j++)
            s[j] = fmaf(P[j], s[j], Sf[j]);
    }

    const int base = b * LENGTH * 256;
    const float* __restrict__ bu  = g_bu    + base;
    const float* __restrict__ Cp  = g_Cv    + base;
    const float* __restrict__ dp  = g_delta + base;
    const float* __restrict__ szp = g_sz    + base;
    float*       __restrict__ yp  = g_y     + base;

    const int t0 = c * TC;
    for (int t = t0; t < t0 + TC; t++) {
        const float delta = dp[t * 256 + d];
        float buv[8], cv[8];
        *(float4*)&buv[0] = *(const float4*)(bu + t * 256 + nb);
        *(float4*)&buv[4] = *(const float4*)(bu + t * 256 + nb + 4);
        *(float4*)&cv[0]  = *(const float4*)(Cp + t * 256 + nb);
        *(float4*)&cv[4]  = *(const float4*)(Cp + t * 256 + nb + 4);

        float yacc = 0.f;
#pragma unroll
        for (int j = 0; j < 8; j++) {
            float p = delta * Ae[j];
            float e;
            asm("ex2.approx.ftz.f32 %0, %1;" : "=f"(e) : "f"(p));
            s[j] = fmaf(e, s[j], delta * buv[j]);
            yacc = fmaf(s[j], cv[j], yacc);
        }
        yacc += __shfl_xor_sync(0xffffffffu, yacc, 16);
        yacc += __shfl_xor_sync(0xffffffffu, yacc, 8);
        yacc += __shfl_xor_sync(0xffffffffu, yacc, 4);
        yacc += __shfl_xor_sync(0xffffffffu, yacc, 2);
        yacc += __shfl_xor_sync(0xffffffffu, yacc, 1);
        if (lane == 0)
            yp[t * 256 + d] = yacc * szp[t * 256 + d];
    }
}

// ---------------------------------------------------------------------------
// Inputs (metadata order): x, W_in, W_delta, W_B, W_C, W_out, A, D(unused)
// ---------------------------------------------------------------------------
extern "C" void kernel_launch(void* const* d_in, const int* in_sizes, int n_in,
                              void* d_out, int out_size)
{
    const float* x       = (const float*)d_in[0];
    const float* W_in    = (const float*)d_in[1];
    const float* W_delta = (const float*)d_in[2];
    const float* W_B     = (const float*)d_in[3];
    const float* W_C     = (const float*)d_in[4];
    const float* W_out   = (const float*)d_in[5];
    const float* A       = (const float*)d_in[6];
    float* out = (float*)d_out;

    // 1) in_proj + split + silu(z)
    gemm_kernel<0><<<dim3(8, 64), 128>>>(x, W_in, nullptr, nullptr, nullptr);
    // 2) delta / bu / Cv projections (fused triple GEMM)
    gemm_kernel<1><<<dim3(12, 64), 128>>>(nullptr, W_delta, W_B, W_C, nullptr);
    // 3) chunked selective scan: pass1 (chunks 0..6), pass2 (fused chunk scan)
    scan_p1<<<(NC - 1) * BATCH * 64, 128>>>(A);
    scan_p2<<<NC * BATCH * 64, 128>>>(A);
    // 4) out_proj
    gemm_kernel<2><<<dim3(2, 64), 128>>>(nullptr, W_out, nullptr, nullptr, out);
}

// round 6
// speedup vs baseline: 1.9872x; 1.0738x over previous
#include <cuda_runtime.h>
#include <cuda_bf16.h>

// Problem constants
#define BATCH   4
#define LENGTH  512
#define DMODEL  128
#define DINNER  256
#define DSTATE  256
#define MROWS   (BATCH * LENGTH)        // 2048
#define LOG2E   1.4426950408889634f
#define NC      8                       // scan chunks
#define TC      64                      // steps per chunk (NC*TC == LENGTH)

// Scratch (allocation-free: __device__ globals)
__device__ float g_xs[MROWS * DINNER];     // xs (first half of in_proj)
__device__ float g_sz[MROWS * DINNER];     // silu(z)
__device__ float g_delta[MROWS * DINNER];  // xs @ W_delta
__device__ float g_bu[MROWS * DSTATE];     // (xs @ W_B) * xs   (elementwise)
__device__ float g_Cv[MROWS * DINNER];     // xs @ W_C
__device__ float g_y[MROWS * DINNER];      // scan output * silu(z)

// Chunked-scan intermediates: layout [((b*NC + c)*256 + d)*256 + n]
__device__ float g_P  [BATCH * NC * DINNER * DSTATE];  // per-chunk prod of a_t
__device__ float g_Sf [BATCH * NC * DINNER * DSTATE];  // per-chunk local final state

// ---------------------------------------------------------------------------
// Tiled fp32 GEMM: C tile 32x64 per block, 128 threads, thread tile 4x4.
// ---------------------------------------------------------------------------
template <int MODE>
__global__ __launch_bounds__(128)
void gemm_kernel(const float* __restrict__ Ag_,
                 const float* __restrict__ B0,
                 const float* __restrict__ B1,
                 const float* __restrict__ B2,
                 float* __restrict__ Og)
{
    constexpr int K   = (MODE == 0) ? 128 : 256;
    constexpr int LDB = (MODE == 0) ? 512 : ((MODE == 1) ? 256 : 128);

    __shared__ float As[16][36];
    __shared__ float Bs[16][68];

    const int tid = threadIdx.x;
    const int tx  = tid & 15;
    const int ty  = tid >> 4;
    const int m0  = blockIdx.y * 32;

    const float* Ag;
    const float* Bg;
    int n0;
    int which = 0;
    if (MODE == 1) {
        which = blockIdx.x >> 2;              // 0: W_delta, 1: W_B, 2: W_C
        n0 = (blockIdx.x & 3) * 64;
        Bg = (which == 0) ? B0 : ((which == 1) ? B1 : B2);
        Ag = g_xs;
    } else {
        n0 = blockIdx.x * 64;
        Bg = B0;
        Ag = (MODE == 0) ? Ag_ : g_y;
    }

    const int aRow  = tid >> 2;
    const int aC4   = (tid & 3) << 2;
    const int bRowk = tid >> 4;
    const int bC4   = (tid & 15) << 2;

    float4 aR;
    float4 bR[2];
    aR = *(const float4*)(Ag + (size_t)(m0 + aRow) * K + aC4);
#pragma unroll
    for (int r = 0; r < 2; r++)
        bR[r] = *(const float4*)(Bg + (size_t)(bRowk + r * 8) * LDB + n0 + bC4);

    float acc[4][4];
#pragma unroll
    for (int i = 0; i < 4; i++)
#pragma unroll
        for (int j = 0; j < 4; j++) acc[i][j] = 0.f;

    for (int k0 = 0; k0 < K; k0 += 16) {
        As[aC4 + 0][aRow] = aR.x;
        As[aC4 + 1][aRow] = aR.y;
        As[aC4 + 2][aRow] = aR.z;
        As[aC4 + 3][aRow] = aR.w;
#pragma unroll
        for (int r = 0; r < 2; r++)
            *(float4*)&Bs[bRowk + r * 8][bC4] = bR[r];
        __syncthreads();

        if (k0 + 16 < K) {
            aR = *(const float4*)(Ag + (size_t)(m0 + aRow) * K + (k0 + 16) + aC4);
#pragma unroll
            for (int r = 0; r < 2; r++)
                bR[r] = *(const float4*)(Bg + (size_t)(k0 + 16 + bRowk + r * 8) * LDB + n0 + bC4);
        }

#pragma unroll
        for (int kk = 0; kk < 16; kk++) {
            float4 av = *(const float4*)&As[kk][ty * 4];
            float4 bv = *(const float4*)&Bs[kk][tx * 4];
            float a[4] = {av.x, av.y, av.z, av.w};
            float b[4] = {bv.x, bv.y, bv.z, bv.w};
#pragma unroll
            for (int i = 0; i < 4; i++)
#pragma unroll
                for (int j = 0; j < 4; j++)
                    acc[i][j] = fmaf(a[i], b[j], acc[i][j]);
        }
        __syncthreads();
    }

#pragma unroll
    for (int i = 0; i < 4; i++) {
        int m = m0 + ty * 4 + i;
#pragma unroll
        for (int j = 0; j < 4; j++) {
            int c = n0 + tx * 4 + j;
            float v = acc[i][j];
            if (MODE == 0) {
                if (c < 256) {
                    g_xs[m * 256 + c] = v;
                } else {
                    float sig = 1.f / (1.f + __expf(-v));
                    g_sz[m * 256 + (c - 256)] = v * sig;   // silu(z)
                }
            } else if (MODE == 1) {
                if (which == 0)      g_delta[m * 256 + c] = v;
                else if (which == 1) g_bu[m * 256 + c] = v * g_xs[m * 256 + c];
                else                 g_Cv[m * 256 + c] = v;
            } else {
                Og[m * 128 + c] = v;
            }
        }
    }
}

// ---------------------------------------------------------------------------
// Scan pass 1: chunks 0..NC-2. Each WARP handles 4 consecutive d's, so the
// n-indexed bu[] loads (shared across all d) are amortized 4x. Per (b,c,d,n):
//   Sf = local final state (zero-init recurrence)
//   P  = exp2(Ae * sum_chunk delta)   (separable exact product of per-step e's)
// ---------------------------------------------------------------------------
__global__ __launch_bounds__(128)
void scan_p1(const float* __restrict__ A)
{
    const int warp = threadIdx.x >> 5;
    const int lane = threadIdx.x & 31;
    int bid = blockIdx.x;                  // ((c*BATCH + b)*16 + dblk)
    const int dblk = bid & 15;  bid >>= 4;
    const int b    = bid & 3;   bid >>= 2;
    const int c    = bid;                  // 0 .. NC-2
    const int d0   = (dblk * 4 + warp) * 4;   // 4 consecutive d's per warp
    const int nb   = lane << 3;

    float Ae[4][8];
#pragma unroll
    for (int di = 0; di < 4; di++)
#pragma unroll
        for (int j = 0; j < 8; j++)
            Ae[di][j] = A[(d0 + di) * 256 + nb + j] * LOG2E;

    const int base = b * LENGTH * 256;
    const float* __restrict__ bu = g_bu    + base;
    const float* __restrict__ dp = g_delta + base;

    float s[4][8], dsum[4];
#pragma unroll
    for (int di = 0; di < 4; di++) {
        dsum[di] = 0.f;
#pragma unroll
        for (int j = 0; j < 8; j++) s[di][j] = 0.f;
    }

    const int t0 = c * TC;
    for (int t = t0; t < t0 + TC; t++) {
        float4 d4 = *(const float4*)(dp + t * 256 + d0);
        float del[4] = {d4.x, d4.y, d4.z, d4.w};
        float buv[8];
        *(float4*)&buv[0] = *(const float4*)(bu + t * 256 + nb);
        *(float4*)&buv[4] = *(const float4*)(bu + t * 256 + nb + 4);
#pragma unroll
        for (int di = 0; di < 4; di++) {
            dsum[di] += del[di];
#pragma unroll
            for (int j = 0; j < 8; j++) {
                float p = del[di] * Ae[di][j];
                float e;
                asm("ex2.approx.ftz.f32 %0, %1;" : "=f"(e) : "f"(p));
                s[di][j] = fmaf(e, s[di][j], del[di] * buv[j]);
            }
        }
    }

#pragma unroll
    for (int di = 0; di < 4; di++) {
        float P[8];
#pragma unroll
        for (int j = 0; j < 8; j++) {
            float p = dsum[di] * Ae[di][j];
            asm("ex2.approx.ftz.f32 %0, %1;" : "=f"(P[j]) : "f"(p));
        }
        const size_t o = ((size_t)((b * NC + c) * 256 + d0 + di)) * 256 + nb;
        *(float4*)(g_P  + o)     = *(float4*)&P[0];
        *(float4*)(g_P  + o + 4) = *(float4*)&P[4];
        *(float4*)(g_Sf + o)     = *(float4*)&s[di][0];
        *(float4*)(g_Sf + o + 4) = *(float4*)&s[di][4];
    }
}

// ---------------------------------------------------------------------------
// Scan pass 2 (fused chunk-summary): each WARP handles 4 consecutive d's.
// Prologue reconstructs 4 initial states from preceding chunks' (P, Sf).
// Per step: one shared bu/cv load serves 4 d's; the 4 n-reductions are done
// in 12 shfls total (2 butterfly rounds on all 4 partials -> select-by-group
// -> 3 rounds within 8-lane groups -> 1 gather); lanes 0-3 write y*silu(z).
// ---------------------------------------------------------------------------
__global__ __launch_bounds__(128)
void scan_p2(const float* __restrict__ A)
{
    const int warp = threadIdx.x >> 5;
    const int lane = threadIdx.x & 31;
    int bid = blockIdx.x;                  // ((c*BATCH + b)*16 + dblk)
    const int dblk = bid & 15;  bid >>= 4;
    const int b    = bid & 3;   bid >>= 2;
    const int c    = bid;                  // 0 .. NC-1
    const int d0   = (dblk * 4 + warp) * 4;
    const int nb   = lane << 3;

    float Ae[4][8];
#pragma unroll
    for (int di = 0; di < 4; di++)
#pragma unroll
        for (int j = 0; j < 8; j++)
            Ae[di][j] = A[(d0 + di) * 256 + nb + j] * LOG2E;

    // Reconstruct initial states from chunks 0..c-1
    float s[4][8];
#pragma unroll
    for (int di = 0; di < 4; di++)
#pragma unroll
        for (int j = 0; j < 8; j++) s[di][j] = 0.f;
    for (int cc = 0; cc < c; cc++) {
#pragma unroll
        for (int di = 0; di < 4; di++) {
            const size_t o = ((size_t)((b * NC + cc) * 256 + d0 + di)) * 256 + nb;
            float P[8], Sf[8];
            *(float4*)&P[0]  = *(const float4*)(g_P  + o);
            *(float4*)&P[4]  = *(const float4*)(g_P  + o + 4);
            *(float4*)&Sf[0] = *(const float4*)(g_Sf + o);
            *(float4*)&Sf[4] = *(const float4*)(g_Sf + o + 4);
#pragma unroll
            for (int j = 0; j < 8; j++)
                s[di][j] = fmaf(P[j], s[di][j], Sf[j]);
        }
    }

    const int base = b * LENGTH * 256;
    const float* __restrict__ bu  = g_bu    + base;
    const float* __restrict__ Cp  = g_Cv    + base;
    const float* __restrict__ dp  = g_delta + base;
    const float* __restrict__ szp = g_sz    + base;
    float*       __restrict__ yp  = g_y     + base;

    const int g = lane >> 3;   // 8-lane group id (selects which d this group reduces)

    const int t0 = c * TC;
    for (int t = t0; t < t0 + TC; t++) {
        float4 d4 = *(const float4*)(dp + t * 256 + d0);
        float del[4] = {d4.x, d4.y, d4.z, d4.w};
        float buv[8], cv[8];
        *(float4*)&buv[0] = *(const float4*)(bu + t * 256 + nb);
        *(float4*)&buv[4] = *(const float4*)(bu + t * 256 + nb + 4);
        *(float4*)&cv[0]  = *(const float4*)(Cp + t * 256 + nb);
        *(float4*)&cv[4]  = *(const float4*)(Cp + t * 256 + nb + 4);

        float y[4];
#pragma unroll
        for (int di = 0; di < 4; di++) {
            float yacc = 0.f;
#pragma unroll
            for (int j = 0; j < 8; j++) {
                float p = del[di] * Ae[di][j];
                float e;
                asm("ex2.approx.ftz.f32 %0, %1;" : "=f"(e) : "f"(p));
                s[di][j] = fmaf(e, s[di][j], del[di] * buv[j]);
                yacc = fmaf(s[di][j], cv[j], yacc);
            }
            y[di] = yacc;
        }

        // 4-way reduction in 12 shfls:
        // phase 1: butterfly xor 8, 16 on all 4 partials ->
        //   y[di](l) = sum over lanes k with k === l (mod 8)
#pragma unroll
        for (int di = 0; di < 4; di++) {
            y[di] += __shfl_xor_sync(0xffffffffu, y[di], 8);
            y[di] += __shfl_xor_sync(0xffffffffu, y[di], 16);
        }
        // phase 2: group g reduces d=g over its 8 lane-classes
        float v = (g == 0) ? y[0] : (g == 1) ? y[1] : (g == 2) ? y[2] : y[3];
        v += __shfl_xor_sync(0xffffffffu, v, 4);
        v += __shfl_xor_sync(0xffffffffu, v, 2);
        v += __shfl_xor_sync(0xffffffffu, v, 1);
        // gather: lane i (<4) takes Y from lane 8i
        float Yl = __shfl_sync(0xffffffffu, v, (lane << 3) & 31);
        if (lane < 4)
            yp[t * 256 + d0 + lane] = Yl * szp[t * 256 + d0 + lane];
    }
}

// ---------------------------------------------------------------------------
// Inputs (metadata order): x, W_in, W_delta, W_B, W_C, W_out, A, D(unused)
// ---------------------------------------------------------------------------
extern "C" void kernel_launch(void* const* d_in, const int* in_sizes, int n_in,
                              void* d_out, int out_size)
{
    const float* x       = (const float*)d_in[0];
    const float* W_in    = (const float*)d_in[1];
    const float* W_delta = (const float*)d_in[2];
    const float* W_B     = (const float*)d_in[3];
    const float* W_C     = (const float*)d_in[4];
    const float* W_out   = (const float*)d_in[5];
    const float* A       = (const float*)d_in[6];
    float* out = (float*)d_out;

    // 1) in_proj + split + silu(z)
    gemm_kernel<0><<<dim3(8, 64), 128>>>(x, W_in, nullptr, nullptr, nullptr);
    // 2) delta / bu / Cv projections (fused triple GEMM)
    gemm_kernel<1><<<dim3(12, 64), 128>>>(nullptr, W_delta, W_B, W_C, nullptr);
    // 3) chunked selective scan: 16 d-groups x 4 warps cover 256 d's
    scan_p1<<<(NC - 1) * BATCH * 16, 128>>>(A);
    scan_p2<<<NC * BATCH * 16, 128>>>(A);
    // 4) out_proj
    gemm_kernel<2><<<dim3(2, 64), 128>>>(nullptr, W_out, nullptr, nullptr, out);
}

// round 7
// speedup vs baseline: 2.1987x; 1.1064x over previous
#include <cuda_runtime.h>
#include <cuda_bf16.h>

// Problem constants
#define BATCH   4
#define LENGTH  512
#define DMODEL  128
#define DINNER  256
#define DSTATE  256
#define MROWS   (BATCH * LENGTH)        // 2048
#define LOG2E   1.4426950408889634f
#define NC      16                      // scan chunks
#define TC      32                      // steps per chunk (NC*TC == LENGTH)

// Scratch (allocation-free: __device__ globals)
__device__ float g_xs[MROWS * DINNER];     // xs (first half of in_proj)
__device__ float g_sz[MROWS * DINNER];     // silu(z)
__device__ float g_delta[MROWS * DINNER];  // xs @ W_delta
__device__ float g_bu[MROWS * DSTATE];     // (xs @ W_B) * xs   (elementwise)
__device__ float g_Cv[MROWS * DINNER];     // xs @ W_C
__device__ float g_y[MROWS * DINNER];      // scan output * silu(z)

// Chunked-scan intermediates: layout [((b*NC + c)*256 + d)*256 + n]
__device__ float g_P  [BATCH * NC * DINNER * DSTATE];  // per-chunk prod of a_t
__device__ float g_Sf [BATCH * NC * DINNER * DSTATE];  // per-chunk local final state

// ---------------------------------------------------------------------------
// Tiled fp32 GEMM: C tile 32x64 per block, 128 threads, thread tile 4x4.
// ---------------------------------------------------------------------------
template <int MODE>
__global__ __launch_bounds__(128)
void gemm_kernel(const float* __restrict__ Ag_,
                 const float* __restrict__ B0,
                 const float* __restrict__ B1,
                 const float* __restrict__ B2,
                 float* __restrict__ Og)
{
    constexpr int K   = (MODE == 0) ? 128 : 256;
    constexpr int LDB = (MODE == 0) ? 512 : ((MODE == 1) ? 256 : 128);

    __shared__ float As[16][36];
    __shared__ float Bs[16][68];

    const int tid = threadIdx.x;
    const int tx  = tid & 15;
    const int ty  = tid >> 4;
    const int m0  = blockIdx.y * 32;

    const float* Ag;
    const float* Bg;
    int n0;
    int which = 0;
    if (MODE == 1) {
        which = blockIdx.x >> 2;              // 0: W_delta, 1: W_B, 2: W_C
        n0 = (blockIdx.x & 3) * 64;
        Bg = (which == 0) ? B0 : ((which == 1) ? B1 : B2);
        Ag = g_xs;
    } else {
        n0 = blockIdx.x * 64;
        Bg = B0;
        Ag = (MODE == 0) ? Ag_ : g_y;
    }

    const int aRow  = tid >> 2;
    const int aC4   = (tid & 3) << 2;
    const int bRowk = tid >> 4;
    const int bC4   = (tid & 15) << 2;

    float4 aR;
    float4 bR[2];
    aR = *(const float4*)(Ag + (size_t)(m0 + aRow) * K + aC4);
#pragma unroll
    for (int r = 0; r < 2; r++)
        bR[r] = *(const float4*)(Bg + (size_t)(bRowk + r * 8) * LDB + n0 + bC4);

    float acc[4][4];
#pragma unroll
    for (int i = 0; i < 4; i++)
#pragma unroll
        for (int j = 0; j < 4; j++) acc[i][j] = 0.f;

    for (int k0 = 0; k0 < K; k0 += 16) {
        As[aC4 + 0][aRow] = aR.x;
        As[aC4 + 1][aRow] = aR.y;
        As[aC4 + 2][aRow] = aR.z;
        As[aC4 + 3][aRow] = aR.w;
#pragma unroll
        for (int r = 0; r < 2; r++)
            *(float4*)&Bs[bRowk + r * 8][bC4] = bR[r];
        __syncthreads();

        if (k0 + 16 < K) {
            aR = *(const float4*)(Ag + (size_t)(m0 + aRow) * K + (k0 + 16) + aC4);
#pragma unroll
            for (int r = 0; r < 2; r++)
                bR[r] = *(const float4*)(Bg + (size_t)(k0 + 16 + bRowk + r * 8) * LDB + n0 + bC4);
        }

#pragma unroll
        for (int kk = 0; kk < 16; kk++) {
            float4 av = *(const float4*)&As[kk][ty * 4];
            float4 bv = *(const float4*)&Bs[kk][tx * 4];
            float a[4] = {av.x, av.y, av.z, av.w};
            float b[4] = {bv.x, bv.y, bv.z, bv.w};
#pragma unroll
            for (int i = 0; i < 4; i++)
#pragma unroll
                for (int j = 0; j < 4; j++)
                    acc[i][j] = fmaf(a[i], b[j], acc[i][j]);
        }
        __syncthreads();
    }

#pragma unroll
    for (int i = 0; i < 4; i++) {
        int m = m0 + ty * 4 + i;
#pragma unroll
        for (int j = 0; j < 4; j++) {
            int c = n0 + tx * 4 + j;
            float v = acc[i][j];
            if (MODE == 0) {
                if (c < 256) {
                    g_xs[m * 256 + c] = v;
                } else {
                    float sig = 1.f / (1.f + __expf(-v));
                    g_sz[m * 256 + (c - 256)] = v * sig;   // silu(z)
                }
            } else if (MODE == 1) {
                if (which == 0)      g_delta[m * 256 + c] = v;
                else if (which == 1) g_bu[m * 256 + c] = v * g_xs[m * 256 + c];
                else                 g_Cv[m * 256 + c] = v;
            } else {
                Og[m * 128 + c] = v;
            }
        }
    }
}

// ---------------------------------------------------------------------------
// Scan pass 1: chunks 0..NC-2. Each WARP handles 2 consecutive d's; regs
// capped at 64 via launch_bounds(128,8) so 32 warps/SM are resident (the
// scan is occupancy-bound: ex2 lat 16 + shfl chains need ~8 warps/SMSP).
//   Sf = local final state (zero-init recurrence)
//   P  = exp2(Ae * sum_chunk delta)   (separable exact product of per-step e's)
// ---------------------------------------------------------------------------
__global__ __launch_bounds__(128, 8)
void scan_p1(const float* __restrict__ A)
{
    const int warp = threadIdx.x >> 5;
    const int lane = threadIdx.x & 31;
    int bid = blockIdx.x;                  // ((c*BATCH + b)*32 + dblk)
    const int dblk = bid & 31;  bid >>= 5;
    const int b    = bid & 3;   bid >>= 2;
    const int c    = bid;                  // 0 .. NC-2
    const int d0   = (dblk * 4 + warp) * 2;   // 2 consecutive d's per warp
    const int nb   = lane << 3;

    float Ae[2][8];
#pragma unroll
    for (int di = 0; di < 2; di++)
#pragma unroll
        for (int j = 0; j < 8; j++)
            Ae[di][j] = A[(d0 + di) * 256 + nb + j] * LOG2E;

    const int base = b * LENGTH * 256;
    const float* __restrict__ bu = g_bu    + base;
    const float* __restrict__ dp = g_delta + base;

    float s[2][8], dsum[2];
#pragma unroll
    for (int di = 0; di < 2; di++) {
        dsum[di] = 0.f;
#pragma unroll
        for (int j = 0; j < 8; j++) s[di][j] = 0.f;
    }

    const int t0 = c * TC;
    for (int t = t0; t < t0 + TC; t++) {
        float2 d2 = *(const float2*)(dp + t * 256 + d0);
        float del[2] = {d2.x, d2.y};
        float buv[8];
        *(float4*)&buv[0] = *(const float4*)(bu + t * 256 + nb);
        *(float4*)&buv[4] = *(const float4*)(bu + t * 256 + nb + 4);
#pragma unroll
        for (int di = 0; di < 2; di++) {
            dsum[di] += del[di];
#pragma unroll
            for (int j = 0; j < 8; j++) {
                float p = del[di] * Ae[di][j];
                float e;
                asm("ex2.approx.ftz.f32 %0, %1;" : "=f"(e) : "f"(p));
                s[di][j] = fmaf(e, s[di][j], del[di] * buv[j]);
            }
        }
    }

#pragma unroll
    for (int di = 0; di < 2; di++) {
        float P[8];
#pragma unroll
        for (int j = 0; j < 8; j++) {
            float p = dsum[di] * Ae[di][j];
            asm("ex2.approx.ftz.f32 %0, %1;" : "=f"(P[j]) : "f"(p));
        }
        const size_t o = ((size_t)((b * NC + c) * 256 + d0 + di)) * 256 + nb;
        *(float4*)(g_P  + o)     = *(float4*)&P[0];
        *(float4*)(g_P  + o + 4) = *(float4*)&P[4];
        *(float4*)(g_Sf + o)     = *(float4*)&s[di][0];
        *(float4*)(g_Sf + o + 4) = *(float4*)&s[di][4];
    }
}

// ---------------------------------------------------------------------------
// Scan pass 2 (fused chunk-summary): each WARP handles 2 consecutive d's.
// Prologue reconstructs both initial states from preceding chunks' (P, Sf).
// Per step: shared bu/cv loads serve both d's; the 2 n-reductions take
// 7 shfls (xor16 x2 -> half-select -> xor8/4/2/1 -> 1 gather); lanes 0-1
// write y*silu(z).
// ---------------------------------------------------------------------------
__global__ __launch_bounds__(128, 8)
void scan_p2(const float* __restrict__ A)
{
    const int warp = threadIdx.x >> 5;
    const int lane = threadIdx.x & 31;
    int bid = blockIdx.x;                  // ((c*BATCH + b)*32 + dblk)
    const int dblk = bid & 31;  bid >>= 5;
    const int b    = bid & 3;   bid >>= 2;
    const int c    = bid;                  // 0 .. NC-1
    const int d0   = (dblk * 4 + warp) * 2;
    const int nb   = lane << 3;

    float Ae[2][8];
#pragma unroll
    for (int di = 0; di < 2; di++)
#pragma unroll
        for (int j = 0; j < 8; j++)
            Ae[di][j] = A[(d0 + di) * 256 + nb + j] * LOG2E;

    // Reconstruct initial states from chunks 0..c-1
    float s[2][8];
#pragma unroll
    for (int di = 0; di < 2; di++)
#pragma unroll
        for (int j = 0; j < 8; j++) s[di][j] = 0.f;
    for (int cc = 0; cc < c; cc++) {
#pragma unroll
        for (int di = 0; di < 2; di++) {
            const size_t o = ((size_t)((b * NC + cc) * 256 + d0 + di)) * 256 + nb;
            float P[8], Sf[8];
            *(float4*)&P[0]  = *(const float4*)(g_P  + o);
            *(float4*)&P[4]  = *(const float4*)(g_P  + o + 4);
            *(float4*)&Sf[0] = *(const float4*)(g_Sf + o);
            *(float4*)&Sf[4] = *(const float4*)(g_Sf + o + 4);
#pragma unroll
            for (int j = 0; j < 8; j++)
                s[di][j] = fmaf(P[j], s[di][j], Sf[j]);
        }
    }

    const int base = b * LENGTH * 256;
    const float* __restrict__ bu  = g_bu    + base;
    const float* __restrict__ Cp  = g_Cv    + base;
    const float* __restrict__ dp  = g_delta + base;
    const float* __restrict__ szp = g_sz    + base;
    float*       __restrict__ yp  = g_y     + base;

    const int t0 = c * TC;
    for (int t = t0; t < t0 + TC; t++) {
        float2 d2 = *(const float2*)(dp + t * 256 + d0);
        float del[2] = {d2.x, d2.y};
        float buv[8], cv[8];
        *(float4*)&buv[0] = *(const float4*)(bu + t * 256 + nb);
        *(float4*)&buv[4] = *(const float4*)(bu + t * 256 + nb + 4);
        *(float4*)&cv[0]  = *(const float4*)(Cp + t * 256 + nb);
        *(float4*)&cv[4]  = *(const float4*)(Cp + t * 256 + nb + 4);

        float y[2];
#pragma unroll
        for (int di = 0; di < 2; di++) {
            float yacc = 0.f;
#pragma unroll
            for (int j = 0; j < 8; j++) {
                float p = del[di] * Ae[di][j];
                float e;
                asm("ex2.approx.ftz.f32 %0, %1;" : "=f"(e) : "f"(p));
                s[di][j] = fmaf(e, s[di][j], del[di] * buv[j]);
                yacc = fmaf(s[di][j], cv[j], yacc);
            }
            y[di] = yacc;
        }

        // 2-way reduction in 7 shfls:
        // xor16 on both partials -> lower half owns d0, upper half owns d0+1
        y[0] += __shfl_xor_sync(0xffffffffu, y[0], 16);
        y[1] += __shfl_xor_sync(0xffffffffu, y[1], 16);
        float v = (lane < 16) ? y[0] : y[1];
        v += __shfl_xor_sync(0xffffffffu, v, 8);
        v += __shfl_xor_sync(0xffffffffu, v, 4);
        v += __shfl_xor_sync(0xffffffffu, v, 2);
        v += __shfl_xor_sync(0xffffffffu, v, 1);
        // lane 0 has y[d0] total, lane 16 has y[d0+1] total
        float Yl = __shfl_sync(0xffffffffu, v, (lane & 1) << 4);
        if (lane < 2)
            yp[t * 256 + d0 + lane] = Yl * szp[t * 256 + d0 + lane];
    }
}

// ---------------------------------------------------------------------------
// Inputs (metadata order): x, W_in, W_delta, W_B, W_C, W_out, A, D(unused)
// ---------------------------------------------------------------------------
extern "C" void kernel_launch(void* const* d_in, const int* in_sizes, int n_in,
                              void* d_out, int out_size)
{
    const float* x       = (const float*)d_in[0];
    const float* W_in    = (const float*)d_in[1];
    const float* W_delta = (const float*)d_in[2];
    const float* W_B     = (const float*)d_in[3];
    const float* W_C     = (const float*)d_in[4];
    const float* W_out   = (const float*)d_in[5];
    const float* A       = (const float*)d_in[6];
    float* out = (float*)d_out;

    // 1) in_proj + split + silu(z)
    gemm_kernel<0><<<dim3(8, 64), 128>>>(x, W_in, nullptr, nullptr, nullptr);
    // 2) delta / bu / Cv projections (fused triple GEMM)
    gemm_kernel<1><<<dim3(12, 64), 128>>>(nullptr, W_delta, W_B, W_C, nullptr);
    // 3) chunked selective scan: 32 d-group blocks x 4 warps x 2 d's = 256 d's
    scan_p1<<<(NC - 1) * BATCH * 32, 128>>>(A);
    scan_p2<<<NC * BATCH * 32, 128>>>(A);
    // 4) out_proj
    gemm_kernel<2><<<dim3(2, 64), 128>>>(nullptr, W_out, nullptr, nullptr, out);
}